// round 12
// baseline (speedup 1.0000x reference)
#include <cuda_runtime.h>
#include <cuda_fp16.h>
#include <cstdint>

#define EPSV 1e-5f
#define N4K  4096
#define BROWS 512

// ---------------- scratch (static __device__: allocation-free) ----------------
__device__ __half g_Mth[(size_t)N4K * N4K];   // injected matrix, TRANSPOSED [j][i], fp16
__device__ __half g_Ah[(size_t)BROWS * N4K];  // x rounded to fp16
__device__ float g_invcmn[N4K];
__device__ float g_invrn[BROWS];

// ---------------- helpers ----------------
__device__ __forceinline__ uint32_t s2u(const void* p) {
    uint32_t a;
    asm("{ .reg .u64 t; cvta.to.shared.u64 t, %1; cvt.u32.u64 %0, t; }" : "=r"(a) : "l"(p));
    return a;
}
__device__ __forceinline__ void ldsm4(uint32_t& r0, uint32_t& r1, uint32_t& r2,
                                      uint32_t& r3, uint32_t addr) {
    asm volatile("ldmatrix.sync.aligned.m8n8.x4.shared.b16 {%0,%1,%2,%3}, [%4];"
                 : "=r"(r0), "=r"(r1), "=r"(r2), "=r"(r3) : "r"(addr));
}
__device__ __forceinline__ void mma_f16(float& d0, float& d1, float& d2, float& d3,
                                        uint32_t a0, uint32_t a1, uint32_t a2, uint32_t a3,
                                        uint32_t b0, uint32_t b1) {
    asm volatile(
        "mma.sync.aligned.m16n8k16.row.col.f32.f16.f16.f32 "
        "{%0,%1,%2,%3}, {%4,%5,%6,%7}, {%8,%9}, {%0,%1,%2,%3};"
        : "+f"(d0), "+f"(d1), "+f"(d2), "+f"(d3)
        : "r"(a0), "r"(a1), "r"(a2), "r"(a3), "r"(b0), "r"(b1));
}
__device__ __forceinline__ void cpasync16(uint32_t dst, const void* src) {
    asm volatile("cp.async.cg.shared.global [%0], [%1], 16;" :: "r"(dst), "l"(src) : "memory");
}
#define SWZ(o) ((o) ^ (((o) >> 3) & 0x70))

// ---------------- K1: fully fused prep ----------------
// blocks [0,128): strip CTAs — 32 w-columns each. Pass 1: colsq(w strip) from
// DRAM. Pass 2: re-read strip from L2, stream qf, write fp16 Mth, accumulate
// full-column sum(m^2) in registers -> finalize g_invcmn in-kernel.
// blocks [128,192): row norms of x + fp16 convert (8 rows per block).
__global__ __launch_bounds__(256) void k_fused(const float* __restrict__ x,
                                               const float* __restrict__ w,
                                               const float* __restrict__ qf,
                                               const int* __restrict__ qit,
                                               const int* __restrict__ iters) {
    int blk = blockIdx.x, tid = threadIdx.x;
    if (blk >= 128) {
        int wp = tid >> 5, lid = tid & 31;
        int b = (blk - 128) * 8 + wp;
        const float4* p = (const float4*)(x + (size_t)b * N4K);
        __half* hrow = g_Ah + (size_t)b * N4K;
        float s = 0.f;
#pragma unroll
        for (int i = 0; i < 32; i++) {
            float4 v = p[lid + i * 32];
            s += v.x * v.x + v.y * v.y + v.z * v.z + v.w * v.w;
            __half2 h0 = __floats2half2_rn(v.x, v.y);
            __half2 h1 = __floats2half2_rn(v.z, v.w);
            uint2 u; u.x = *(uint32_t*)&h0; u.y = *(uint32_t*)&h1;
            *(uint2*)&hrow[(size_t)(lid + i * 32) * 4] = u;
        }
#pragma unroll
        for (int o = 16; o; o >>= 1) s += __shfl_xor_sync(0xFFFFFFFFu, s, o);
        if (lid == 0) g_invrn[b] = 1.0f / fmaxf(sqrtf(s), EPSV);
        return;
    }

    __shared__ float swt[32][68];     // transposed w tile [j-local][i-local(64)]
    __shared__ float sred[8][32];
    __shared__ float sicw[32];
    int j0 = blk * 32;
    int lane = tid & 31, wp = tid >> 5;

    // ---- pass 1: column sumsq of this 32-column strip ----
    {
        float a = 0.f;
        const float* p = w + (size_t)wp * N4K + j0 + lane;
#pragma unroll 16
        for (int i = 0; i < 512; i++) {
            float v = p[(size_t)i * 8 * N4K];
            a += v * v;
        }
        sred[wp][lane] = a;
        __syncthreads();
        if (tid < 32) {
            float s = 0.f;
#pragma unroll
            for (int r = 0; r < 8; r++) s += sred[r][tid];
            sicw[tid] = 1.0f / fmaxf(sqrtf(s), EPSV);
        }
        __syncthreads();
    }

    // ---- pass 2: build Mth rows for j0..j0+31, accumulate sum(m^2) ----
    int it = *iters + 1;
    int jl = tid >> 3;                 // 0..31
    int ig = (tid & 7) * 8;            // 0..56
    float icw = sicw[jl];
    float msum = 0.f;
    const float* qrow = qf + (size_t)(j0 + jl) * N4K;
    __half* mrow = g_Mth + (size_t)(j0 + jl) * N4K;

    for (int ic = 0; ic < 64; ic++) {
        int i0 = ic * 64;
#pragma unroll
        for (int r = 0; r < 2; r++) {
            int f = tid + 256 * r;
            int row = f >> 3, c4 = (f & 7) * 4;
            float4 v = *(const float4*)&w[(size_t)(i0 + row) * N4K + j0 + c4];
            swt[c4 + 0][row] = v.x; swt[c4 + 1][row] = v.y;
            swt[c4 + 2][row] = v.z; swt[c4 + 3][row] = v.w;
        }
        __syncthreads();

        int4 q0 = *(const int4*)&qit[i0 + ig];
        int4 q1 = *(const int4*)&qit[i0 + ig + 4];
        float4 qa = *(const float4*)&qrow[i0 + ig];
        float4 qb = *(const float4*)&qrow[i0 + ig + 4];
        float4 wa = *(const float4*)&swt[jl][ig];
        float4 wb = *(const float4*)&swt[jl][ig + 4];
        int qi[8] = {q0.x, q0.y, q0.z, q0.w, q1.x, q1.y, q1.z, q1.w};
        float qv[8] = {qa.x, qa.y, qa.z, qa.w, qb.x, qb.y, qb.z, qb.w};
        float wv[8] = {wa.x, wa.y, wa.z, wa.w, wb.x, wb.y, wb.z, wb.w};
        uint32_t pk[4];
#pragma unroll
        for (int u = 0; u < 4; u++) {
            float qla = ((it > 8000) && (it - qi[2 * u]     <= 200)) ? 0.15f : 0.0f;
            float qlb = ((it > 8000) && (it - qi[2 * u + 1] <= 200)) ? 0.15f : 0.0f;
            float m0 = wv[2 * u]     * icw * (1.f - qla) + qv[2 * u]     * qla;
            float m1 = wv[2 * u + 1] * icw * (1.f - qlb) + qv[2 * u + 1] * qlb;
            __half2 h = __floats2half2_rn(m0, m1);
            pk[u] = *(uint32_t*)&h;
            float f0 = __low2float(h), f1 = __high2float(h);
            msum += f0 * f0 + f1 * f1;
        }
        *(uint4*)&mrow[i0 + ig] = make_uint4(pk[0], pk[1], pk[2], pk[3]);
        __syncthreads();
    }
    // reduce msum over the 8 lanes sharing jl (consecutive lanes in a warp)
    msum += __shfl_xor_sync(0xFFFFFFFFu, msum, 1);
    msum += __shfl_xor_sync(0xFFFFFFFFu, msum, 2);
    msum += __shfl_xor_sync(0xFFFFFFFFu, msum, 4);
    if ((tid & 7) == 0)
        g_invcmn[j0 + jl] = 1.0f / fmaxf(sqrtf(msum), EPSV);
}

// ---------------- K2: fp16 mma.sync GEMM, 128 threads, 64x64 warp tiles ----------------
// BM=128, BN=128, BK=64; 4 warps (2m x 2n), warp tile 64x64, m16n8k16.
// 3-stage cp.async (32KB/stage), 2 CTAs per SM.
static constexpr int STAGE_B = 32768;
static constexpr int SMEM_DYN = 1024 + 3 * STAGE_B;
static constexpr int NKT = 64;                 // k-tiles of 64

__global__ __launch_bounds__(128, 2)
void k_gemm_mma(float* __restrict__ out) {
    extern __shared__ char smraw[];
    uint32_t raw = s2u(smraw);
    uint32_t sb = (raw + 1023) & ~1023u;       // 1024-aligned base

    int tid = threadIdx.x;
    int lane = tid & 31, wid = tid >> 5;
    int wm = (wid >> 1) * 64;                  // warp m offset (0,64)
    int wn = (wid & 1) * 64;                   // warp n offset (0,64)
    int bn0 = blockIdx.x * 128, bm0 = blockIdx.y * 128;

    // ldmatrix per-lane addressing
    int q = lane >> 3, rr = lane & 7;
    uint32_t qk = (uint32_t)(q >> 1) * 16;     // +16B for high-k quads
    uint32_t xr = (uint32_t)(rr << 4);         // swizzle XOR
    int aRowL = wm + (q & 1) * 8 + rr;
    int bRowL = wn + (q & 1) * 8 + rr;

    float acc[4][8][4];
#pragma unroll
    for (int mt = 0; mt < 4; mt++)
#pragma unroll
        for (int n8 = 0; n8 < 8; n8++)
#pragma unroll
            for (int c = 0; c < 4; c++) acc[mt][n8][c] = 0.f;

#define LOADSTAGE(st, t)                                                          \
    {                                                                             \
        uint32_t base = sb + (uint32_t)(st) * STAGE_B;                            \
        size_t k0 = (size_t)(t) * 64;                                             \
        _Pragma("unroll")                                                         \
        for (int i = 0; i < 8; i++) {                                             \
            int fid = tid + 128 * i;                                              \
            int r = fid >> 3, c = fid & 7;                                        \
            uint32_t so = SWZ((uint32_t)(r * 128 + c * 16));                      \
            cpasync16(base + so, &g_Ah[(size_t)(bm0 + r) * N4K + k0 + c * 8]);    \
            cpasync16(base + 16384u + so,                                         \
                      &g_Mth[(size_t)(bn0 + r) * N4K + k0 + c * 8]);              \
        }                                                                         \
    }
#define COMMIT() asm volatile("cp.async.commit_group;" ::: "memory")

    LOADSTAGE(0, 0); COMMIT();
    LOADSTAGE(1, 1); COMMIT();

    int cur = 0, nxt = 2;
    for (int t = 0; t < NKT; t++) {
        asm volatile("cp.async.wait_group 1;" ::: "memory");
        __syncthreads();
        if (t + 2 < NKT) { LOADSTAGE(nxt, t + 2); }
        COMMIT();

        uint32_t sa = sb + (uint32_t)cur * STAGE_B;
        uint32_t sB = sa + 16384u;
#pragma unroll
        for (int ks = 0; ks < 4; ks++) {
            uint32_t kb = ((uint32_t)(ks * 32) + qk) ^ xr;
            uint32_t a[4][4], b[4][4];
#pragma unroll
            for (int mt = 0; mt < 4; mt++)
                ldsm4(a[mt][0], a[mt][1], a[mt][2], a[mt][3],
                      sa + (uint32_t)(aRowL + mt * 16) * 128 + kb);
#pragma unroll
            for (int nt = 0; nt < 4; nt++)
                ldsm4(b[nt][0], b[nt][1], b[nt][2], b[nt][3],
                      sB + (uint32_t)(bRowL + nt * 16) * 128 + kb);
#pragma unroll
            for (int mt = 0; mt < 4; mt++)
#pragma unroll
                for (int n8 = 0; n8 < 8; n8++)
                    mma_f16(acc[mt][n8][0], acc[mt][n8][1], acc[mt][n8][2], acc[mt][n8][3],
                            a[mt][0], a[mt][1], a[mt][2], a[mt][3],
                            b[n8 >> 1][n8 & 1], b[n8 >> 1][(n8 & 1) + 2]);
        }
        cur = (cur == 2) ? 0 : cur + 1;
        nxt = (nxt == 2) ? 0 : nxt + 1;
    }

    // ---- epilogue: fold row + column norms (invcmn direct from gmem, L2-hot) ----
    int g4 = lane >> 2, t4 = lane & 3;
#pragma unroll
    for (int mt = 0; mt < 4; mt++) {
        int row0 = bm0 + wm + mt * 16 + g4;
        int row1 = row0 + 8;
        float ir0 = g_invrn[row0], ir1 = g_invrn[row1];
#pragma unroll
        for (int n8 = 0; n8 < 8; n8++) {
            int col = bn0 + wn + n8 * 8 + 2 * t4;
            float c0 = g_invcmn[col], c1 = g_invcmn[col + 1];
            float2 v0 = make_float2(acc[mt][n8][0] * ir0 * c0, acc[mt][n8][1] * ir0 * c1);
            float2 v1 = make_float2(acc[mt][n8][2] * ir1 * c0, acc[mt][n8][3] * ir1 * c1);
            *(float2*)&out[(size_t)row0 * N4K + col] = v0;
            *(float2*)&out[(size_t)row1 * N4K + col] = v1;
        }
    }
}

// ---------------- launch ----------------
extern "C" void kernel_launch(void* const* d_in, const int* in_sizes, int n_in,
                              void* d_out, int out_size) {
    const float* x   = (const float*)d_in[0];   // (512, 4096)
    const float* w   = (const float*)d_in[1];   // (4096, 4096)
    const float* qf  = (const float*)d_in[2];   // (4096, 4096)
    const int*   qit = (const int*)d_in[3];     // (4096,)
    const int*   it  = (const int*)d_in[4];     // scalar
    float* out = (float*)d_out;                 // (512, 4096) fp32

    cudaFuncSetAttribute(k_gemm_mma, cudaFuncAttributeMaxDynamicSharedMemorySize, SMEM_DYN);

    k_fused<<<192, 256>>>(x, w, qf, qit, it);
    k_gemm_mma<<<dim3(32, 4), 128, SMEM_DYN>>>(out);
}

// round 13
// speedup vs baseline: 1.0651x; 1.0651x over previous
#include <cuda_runtime.h>
#include <cuda_fp16.h>
#include <cstdint>

#define EPSV 1e-5f
#define N4K  4096
#define BROWS 512

// ---------------- scratch (static __device__: allocation-free) ----------------
__device__ __half g_Mth[(size_t)N4K * N4K];   // injected matrix, TRANSPOSED [j][i], fp16
__device__ __half g_Ah[(size_t)BROWS * N4K];  // x rounded to fp16
__device__ float g_cw_part[16][N4K];          // partial col sumsq of weight
__device__ float g_cm_part[64][N4K];          // partial col sumsq of Mth
__device__ float g_invrn[BROWS];
__device__ float g_ql[N4K];
__device__ int   g_cnt[32];                   // per-128-col-block build completion count

// ---------------- helpers ----------------
__device__ __forceinline__ uint32_t s2u(const void* p) {
    uint32_t a;
    asm("{ .reg .u64 t; cvta.to.shared.u64 t, %1; cvt.u32.u64 %0, t; }" : "=r"(a) : "l"(p));
    return a;
}
__device__ __forceinline__ void ldsm4(uint32_t& r0, uint32_t& r1, uint32_t& r2,
                                      uint32_t& r3, uint32_t addr) {
    asm volatile("ldmatrix.sync.aligned.m8n8.x4.shared.b16 {%0,%1,%2,%3}, [%4];"
                 : "=r"(r0), "=r"(r1), "=r"(r2), "=r"(r3) : "r"(addr));
}
__device__ __forceinline__ void mma_f16(float& d0, float& d1, float& d2, float& d3,
                                        uint32_t a0, uint32_t a1, uint32_t a2, uint32_t a3,
                                        uint32_t b0, uint32_t b1) {
    asm volatile(
        "mma.sync.aligned.m16n8k16.row.col.f32.f16.f16.f32 "
        "{%0,%1,%2,%3}, {%4,%5,%6,%7}, {%8,%9}, {%0,%1,%2,%3};"
        : "+f"(d0), "+f"(d1), "+f"(d2), "+f"(d3)
        : "r"(a0), "r"(a1), "r"(a2), "r"(a3), "r"(b0), "r"(b1));
}
__device__ __forceinline__ void cpasync16(uint32_t dst, const void* src) {
    asm volatile("cp.async.cg.shared.global [%0], [%1], 16;" :: "r"(dst), "l"(src) : "memory");
}
#define SWZ(o) ((o) ^ (((o) >> 3) & 0x70))

// ---------------- K1: fused rownorm(x)+fp16  AND  colsq(w)+ql  (+ flag reset) ----------------
__global__ void k_pre(const float* __restrict__ x, const float* __restrict__ w,
                      const int* __restrict__ qit, const int* __restrict__ iters) {
    int blk = blockIdx.x;
    if (blk == 0 && threadIdx.x < 32) g_cnt[threadIdx.x] = 0;
    if (blk < 64) {
        int wp = threadIdx.x >> 5, lid = threadIdx.x & 31;
        int b = blk * 8 + wp;
        const float4* p = (const float4*)(x + (size_t)b * N4K);
        __half* hrow = g_Ah + (size_t)b * N4K;
        float s = 0.f;
#pragma unroll
        for (int i = 0; i < 32; i++) {
            float4 v = p[lid + i * 32];
            s += v.x * v.x + v.y * v.y + v.z * v.z + v.w * v.w;
            __half2 h0 = __floats2half2_rn(v.x, v.y);
            __half2 h1 = __floats2half2_rn(v.z, v.w);
            uint2 u; u.x = *(uint32_t*)&h0; u.y = *(uint32_t*)&h1;
            *(uint2*)&hrow[(size_t)(lid + i * 32) * 4] = u;
        }
#pragma unroll
        for (int o = 16; o; o >>= 1) s += __shfl_xor_sync(0xFFFFFFFFu, s, o);
        if (lid == 0) g_invrn[b] = 1.0f / fmaxf(sqrtf(s), EPSV);
    } else {
        int jb = blk - 64;
        int j = (jb & 15) * 256 + threadIdx.x;
        int s = jb >> 4;
        if (s == 0) {
            int it = *iters + 1;
            bool active = (it - qit[j]) <= 200;
            g_ql[j] = ((it > 8000) && active) ? 0.15f : 0.0f;
        }
        const float* p = w + (size_t)(s * 256) * N4K + j;
        float acc = 0.f;
#pragma unroll 16
        for (int r = 0; r < 256; r++) { float v = p[(size_t)r * N4K]; acc += v * v; }
        g_cw_part[s][j] = acc;
    }
}

// ---------------- K2: combined build + GEMM with flag-based overlap ----------------
// bids [0,128): GEMM CTAs (placed first; spin on their 128-col block's flag).
// bids [128,4224): build CTAs, j-major (jblk = (bid-128)>>6, iblk = (bid-128)&63)
//   so the builds for n-block 0 are the first build bids placed.
static constexpr int STAGE_B = 32768;
static constexpr int SMEM_DYN = 1024 + 3 * STAGE_B + 512;
static constexpr int NKT = 64;

__global__ __launch_bounds__(256, 2)
void k_main(const float* __restrict__ w, const float* __restrict__ qf,
            float* __restrict__ out) {
    extern __shared__ char smraw[];
    int tid = threadIdx.x;
    int bid = blockIdx.x;

    if (bid >= 128) {
        // ================= build CTA (R9 tile code, dynamic smem) =================
        int b = bid - 128;
        int jblk = b >> 6, iblk = b & 63;
        int i0 = iblk * 64, j0 = jblk * 64;
        float (*swt)[68] = (float(*)[68])smraw;           // 64*68*4 = 17408 B
        float* sicw = (float*)(smraw + 17408);

        if (tid < 64) {
            float s = 0.f;
#pragma unroll
            for (int p = 0; p < 16; p++) s += g_cw_part[p][j0 + tid];
            sicw[tid] = 1.0f / fmaxf(sqrtf(s), EPSV);
        }
#pragma unroll
        for (int c = 0; c < 4; c++) {
            int chunk = tid + 256 * c;
            int il = chunk >> 4, jq = (chunk & 15) * 4;
            float4 v = *(const float4*)&w[(size_t)(i0 + il) * N4K + j0 + jq];
            swt[jq + 0][il] = v.x; swt[jq + 1][il] = v.y;
            swt[jq + 2][il] = v.z; swt[jq + 3][il] = v.w;
        }
        __syncthreads();

        int iq = (tid & 15) * 4;
        float4 q4 = *(const float4*)&g_ql[i0 + iq];
        float4 o4 = make_float4(1.f - q4.x, 1.f - q4.y, 1.f - q4.z, 1.f - q4.w);
        float part[4];
#pragma unroll
        for (int c = 0; c < 4; c++) {
            int jl = (tid >> 4) + 16 * c;
            int j = j0 + jl;
            float icw = sicw[jl];
            float4 wv = *(const float4*)&swt[jl][iq];
            float4 qv = *(const float4*)&qf[(size_t)j * N4K + i0 + iq];
            float m0 = wv.x * icw * o4.x + qv.x * q4.x;
            float m1 = wv.y * icw * o4.y + qv.y * q4.y;
            float m2 = wv.z * icw * o4.z + qv.z * q4.z;
            float m3 = wv.w * icw * o4.w + qv.w * q4.w;
            __half2 h0 = __floats2half2_rn(m0, m1);
            __half2 h1 = __floats2half2_rn(m2, m3);
            uint2 u; u.x = *(uint32_t*)&h0; u.y = *(uint32_t*)&h1;
            *(uint2*)&g_Mth[(size_t)j * N4K + i0 + iq] = u;
            float f0 = __low2float(h0), f1 = __high2float(h0);
            float f2 = __low2float(h1), f3 = __high2float(h1);
            part[c] = f0 * f0 + f1 * f1 + f2 * f2 + f3 * f3;
        }
#pragma unroll
        for (int c = 0; c < 4; c++) {
            float s = part[c];
            s += __shfl_xor_sync(0xFFFFFFFFu, s, 1);
            s += __shfl_xor_sync(0xFFFFFFFFu, s, 2);
            s += __shfl_xor_sync(0xFFFFFFFFu, s, 4);
            s += __shfl_xor_sync(0xFFFFFFFFu, s, 8);
            if ((tid & 15) == 0)
                g_cm_part[iblk][j0 + (tid >> 4) + 16 * c] = s;
        }
        // signal: all stores visible, then count this CTA
        __threadfence();
        __syncthreads();
        if (tid == 0) atomicAdd(&g_cnt[jblk >> 1], 1);
        return;
    }

    // ================= GEMM CTA (R8 body: 8 warps, 64x32 warp tiles, 3-stage) =================
    int gi = bid;
    int bn0 = (gi >> 2) * 128, bm0 = (gi & 3) * 128;
    int g = gi >> 2;

    // wait for this n-block's 128 producer CTAs
    if (tid == 0) {
        while (atomicAdd(&g_cnt[g], 0) < 128) __nanosleep(256);
    }
    __syncthreads();
    __threadfence();

    uint32_t raw = s2u(smraw);
    uint32_t sb = (raw + 1023) & ~1023u;
    char* smp = smraw + (sb - raw);
    float* sic = (float*)(smp + 3 * STAGE_B);

    int lane = tid & 31, wid = tid >> 5;
    int wm = (wid >> 2) * 64;
    int wn = (wid & 3) * 32;

    int q = lane >> 3, rr = lane & 7;
    uint32_t qk = (uint32_t)(q >> 1) * 16;
    uint32_t xr = (uint32_t)(rr << 4);
    int aRowL = wm + (q & 1) * 8 + rr;
    int bRowL = wn + (q & 1) * 8 + rr;

    float acc[4][4][4];
#pragma unroll
    for (int mt = 0; mt < 4; mt++)
#pragma unroll
        for (int n8 = 0; n8 < 4; n8++)
#pragma unroll
            for (int c = 0; c < 4; c++) acc[mt][n8][c] = 0.f;

#define LOADSTAGE(st, t)                                                          \
    {                                                                             \
        uint32_t base = sb + (uint32_t)(st) * STAGE_B;                            \
        size_t k0 = (size_t)(t) * 64;                                             \
        _Pragma("unroll")                                                         \
        for (int i = 0; i < 4; i++) {                                             \
            int fid = tid + 256 * i;                                              \
            int r = fid >> 3, c = fid & 7;                                        \
            uint32_t so = SWZ((uint32_t)(r * 128 + c * 16));                      \
            cpasync16(base + so, &g_Ah[(size_t)(bm0 + r) * N4K + k0 + c * 8]);    \
            cpasync16(base + 16384u + so,                                         \
                      &g_Mth[(size_t)(bn0 + r) * N4K + k0 + c * 8]);              \
        }                                                                         \
    }
#define COMMIT() asm volatile("cp.async.commit_group;" ::: "memory")

    LOADSTAGE(0, 0); COMMIT();
    LOADSTAGE(1, 1); COMMIT();

    // invcmn finalize for this CTA's 128 columns (L2-resident partials)
    {
        int c = tid >> 1, ph = tid & 1;
        float s = 0.f;
#pragma unroll
        for (int p = 0; p < 32; p++) s += __ldcg(&g_cm_part[2 * p + ph][bn0 + c]);
        s += __shfl_xor_sync(0xFFFFFFFFu, s, 1);
        if (ph == 0) sic[c] = 1.0f / fmaxf(sqrtf(s), EPSV);
    }

    int cur = 0, nxt = 2;
    for (int t = 0; t < NKT; t++) {
        asm volatile("cp.async.wait_group 1;" ::: "memory");
        __syncthreads();
        if (t + 2 < NKT) { LOADSTAGE(nxt, t + 2); }
        COMMIT();

        uint32_t sa = sb + (uint32_t)cur * STAGE_B;
        uint32_t sB = sa + 16384u;
#pragma unroll
        for (int ks = 0; ks < 4; ks++) {
            uint32_t kb = ((uint32_t)(ks * 32) + qk) ^ xr;
            uint32_t a[4][4], b[2][4];
#pragma unroll
            for (int mt = 0; mt < 4; mt++)
                ldsm4(a[mt][0], a[mt][1], a[mt][2], a[mt][3],
                      sa + (uint32_t)(aRowL + mt * 16) * 128 + kb);
#pragma unroll
            for (int nt = 0; nt < 2; nt++)
                ldsm4(b[nt][0], b[nt][1], b[nt][2], b[nt][3],
                      sB + (uint32_t)(bRowL + nt * 16) * 128 + kb);
#pragma unroll
            for (int mt = 0; mt < 4; mt++)
#pragma unroll
                for (int n8 = 0; n8 < 4; n8++)
                    mma_f16(acc[mt][n8][0], acc[mt][n8][1], acc[mt][n8][2], acc[mt][n8][3],
                            a[mt][0], a[mt][1], a[mt][2], a[mt][3],
                            b[n8 >> 1][n8 & 1], b[n8 >> 1][(n8 & 1) + 2]);
        }
        cur = (cur == 2) ? 0 : cur + 1;
        nxt = (nxt == 2) ? 0 : nxt + 1;
    }

    // epilogue: fold row + column norms, write fp32
    int g4 = lane >> 2, t4 = lane & 3;
#pragma unroll
    for (int mt = 0; mt < 4; mt++) {
        int row0 = bm0 + wm + mt * 16 + g4;
        int row1 = row0 + 8;
        float ir0 = g_invrn[row0], ir1 = g_invrn[row1];
#pragma unroll
        for (int n8 = 0; n8 < 4; n8++) {
            int cl = wn + n8 * 8 + 2 * t4;
            int col = bn0 + cl;
            float c0 = sic[cl], c1 = sic[cl + 1];
            float2 v0 = make_float2(acc[mt][n8][0] * ir0 * c0, acc[mt][n8][1] * ir0 * c1);
            float2 v1 = make_float2(acc[mt][n8][2] * ir1 * c0, acc[mt][n8][3] * ir1 * c1);
            *(float2*)&out[(size_t)row0 * N4K + col] = v0;
            *(float2*)&out[(size_t)row1 * N4K + col] = v1;
        }
    }
}

// ---------------- launch ----------------
extern "C" void kernel_launch(void* const* d_in, const int* in_sizes, int n_in,
                              void* d_out, int out_size) {
    const float* x   = (const float*)d_in[0];   // (512, 4096)
    const float* w   = (const float*)d_in[1];   // (4096, 4096)
    const float* qf  = (const float*)d_in[2];   // (4096, 4096)
    const int*   qit = (const int*)d_in[3];     // (4096,)
    const int*   it  = (const int*)d_in[4];     // scalar
    float* out = (float*)d_out;                 // (512, 4096) fp32

    cudaFuncSetAttribute(k_main, cudaFuncAttributeMaxDynamicSharedMemorySize, SMEM_DYN);

    k_pre<<<320, 256>>>(x, w, qit, it);
    k_main<<<128 + 64 * 64, 256, SMEM_DYN>>>(w, qf, out);
}

// round 14
// speedup vs baseline: 1.1819x; 1.1096x over previous
#include <cuda_runtime.h>
#include <cuda_fp16.h>
#include <cstdint>

#define EPSV 1e-5f
#define N4K  4096
#define BROWS 512

// ---------------- scratch (static __device__: allocation-free) ----------------
__device__ __half g_Mth[(size_t)N4K * N4K];   // injected matrix, TRANSPOSED [j][i], fp16
__device__ __half g_Ah[(size_t)BROWS * N4K];  // x rounded to fp16
__device__ float g_cw_part[16][N4K];          // partial col sumsq of weight
__device__ float g_cm_part[64][N4K];          // partial col sumsq of Mth
__device__ float g_invrn[BROWS];
__device__ float g_ql[N4K];
__device__ int   g_flag[64];                  // per-i-block build completion (counts to 64)

// ---------------- helpers ----------------
__device__ __forceinline__ uint32_t s2u(const void* p) {
    uint32_t a;
    asm("{ .reg .u64 t; cvta.to.shared.u64 t, %1; cvt.u32.u64 %0, t; }" : "=r"(a) : "l"(p));
    return a;
}
__device__ __forceinline__ void ldsm4(uint32_t& r0, uint32_t& r1, uint32_t& r2,
                                      uint32_t& r3, uint32_t addr) {
    asm volatile("ldmatrix.sync.aligned.m8n8.x4.shared.b16 {%0,%1,%2,%3}, [%4];"
                 : "=r"(r0), "=r"(r1), "=r"(r2), "=r"(r3) : "r"(addr));
}
__device__ __forceinline__ void mma_f16(float& d0, float& d1, float& d2, float& d3,
                                        uint32_t a0, uint32_t a1, uint32_t a2, uint32_t a3,
                                        uint32_t b0, uint32_t b1) {
    asm volatile(
        "mma.sync.aligned.m16n8k16.row.col.f32.f16.f16.f32 "
        "{%0,%1,%2,%3}, {%4,%5,%6,%7}, {%8,%9}, {%0,%1,%2,%3};"
        : "+f"(d0), "+f"(d1), "+f"(d2), "+f"(d3)
        : "r"(a0), "r"(a1), "r"(a2), "r"(a3), "r"(b0), "r"(b1));
}
__device__ __forceinline__ void cpasync16(uint32_t dst, const void* src) {
    asm volatile("cp.async.cg.shared.global [%0], [%1], 16;" :: "r"(dst), "l"(src) : "memory");
}
__device__ __forceinline__ void waitflag(int t) {
    volatile int* f = g_flag + t;
    int v = *f;
    while (v < 64) { __nanosleep(128); v = *f; }
}
#define SWZ(o) ((o) ^ (((o) >> 3) & 0x70))

// ---------------- K1: fused rownorm(x)+fp16  AND  colsq(w)+ql  (+ flag reset) ----------------
__global__ void k_pre(const float* __restrict__ x, const float* __restrict__ w,
                      const int* __restrict__ qit, const int* __restrict__ iters) {
    int blk = blockIdx.x;
    if (blk == 0 && threadIdx.x < 64) g_flag[threadIdx.x] = 0;
    if (blk < 64) {
        int wp = threadIdx.x >> 5, lid = threadIdx.x & 31;
        int b = blk * 8 + wp;
        const float4* p = (const float4*)(x + (size_t)b * N4K);
        __half* hrow = g_Ah + (size_t)b * N4K;
        float s = 0.f;
#pragma unroll
        for (int i = 0; i < 32; i++) {
            float4 v = p[lid + i * 32];
            s += v.x * v.x + v.y * v.y + v.z * v.z + v.w * v.w;
            __half2 h0 = __floats2half2_rn(v.x, v.y);
            __half2 h1 = __floats2half2_rn(v.z, v.w);
            uint2 u; u.x = *(uint32_t*)&h0; u.y = *(uint32_t*)&h1;
            *(uint2*)&hrow[(size_t)(lid + i * 32) * 4] = u;
        }
#pragma unroll
        for (int o = 16; o; o >>= 1) s += __shfl_xor_sync(0xFFFFFFFFu, s, o);
        if (lid == 0) g_invrn[b] = 1.0f / fmaxf(sqrtf(s), EPSV);
    } else {
        int jb = blk - 64;
        int j = (jb & 15) * 256 + threadIdx.x;
        int s = jb >> 4;
        if (s == 0) {
            int it = *iters + 1;
            bool active = (it - qit[j]) <= 200;
            g_ql[j] = ((it > 8000) && active) ? 0.15f : 0.0f;
        }
        const float* p = w + (size_t)(s * 256) * N4K + j;
        float acc = 0.f;
#pragma unroll 16
        for (int r = 0; r < 256; r++) { float v = p[(size_t)r * N4K]; acc += v * v; }
        g_cw_part[s][j] = acc;
    }
}

// ---------------- K2: combined build + GEMM, fine-grained i-major overlap ----------------
// bids [0,128): GEMM CTAs. bids [128,4224): build CTAs, I-MAJOR:
//   iblk = (bid-128)>>6, jblk = (bid-128)&63  -> all 64 j-strips of i-block 0 first.
// Build CTA signals g_flag[iblk]++ when its tile is written; a GEMM CTA only
// needs flag[t]==64 before prefetching k-tile t. invcmn is finalized AFTER the
// mainloop (flag[63]==64 implies all builds done).
static constexpr int STAGE_B = 32768;
static constexpr int SMEM_DYN = 1024 + 3 * STAGE_B;
static constexpr int NKT = 64;

__global__ __launch_bounds__(256)
void k_main(const float* __restrict__ w, const float* __restrict__ qf,
            float* __restrict__ out) {
    extern __shared__ char smraw[];
    int tid = threadIdx.x;
    int bid = blockIdx.x;

    if (bid >= 128) {
        // ================= build CTA =================
        int b = bid - 128;
        int iblk = b >> 6, jblk = b & 63;
        int i0 = iblk * 64, j0 = jblk * 64;
        float (*swt)[68] = (float(*)[68])smraw;           // 64*68*4 = 17408 B
        float* sicw = (float*)(smraw + 17408);

        if (tid < 64) {
            float s = 0.f;
#pragma unroll
            for (int p = 0; p < 16; p++) s += g_cw_part[p][j0 + tid];
            sicw[tid] = 1.0f / fmaxf(sqrtf(s), EPSV);
        }
#pragma unroll
        for (int c = 0; c < 4; c++) {
            int chunk = tid + 256 * c;
            int il = chunk >> 4, jq = (chunk & 15) * 4;
            float4 v = *(const float4*)&w[(size_t)(i0 + il) * N4K + j0 + jq];
            swt[jq + 0][il] = v.x; swt[jq + 1][il] = v.y;
            swt[jq + 2][il] = v.z; swt[jq + 3][il] = v.w;
        }
        __syncthreads();

        int iq = (tid & 15) * 4;
        float4 q4 = *(const float4*)&g_ql[i0 + iq];
        float4 o4 = make_float4(1.f - q4.x, 1.f - q4.y, 1.f - q4.z, 1.f - q4.w);
        float part[4];
#pragma unroll
        for (int c = 0; c < 4; c++) {
            int jl = (tid >> 4) + 16 * c;
            int j = j0 + jl;
            float icw = sicw[jl];
            float4 wv = *(const float4*)&swt[jl][iq];
            float4 qv = *(const float4*)&qf[(size_t)j * N4K + i0 + iq];
            float m0 = wv.x * icw * o4.x + qv.x * q4.x;
            float m1 = wv.y * icw * o4.y + qv.y * q4.y;
            float m2 = wv.z * icw * o4.z + qv.z * q4.z;
            float m3 = wv.w * icw * o4.w + qv.w * q4.w;
            __half2 h0 = __floats2half2_rn(m0, m1);
            __half2 h1 = __floats2half2_rn(m2, m3);
            uint2 u; u.x = *(uint32_t*)&h0; u.y = *(uint32_t*)&h1;
            *(uint2*)&g_Mth[(size_t)j * N4K + i0 + iq] = u;
            float f0 = __low2float(h0), f1 = __high2float(h0);
            float f2 = __low2float(h1), f3 = __high2float(h1);
            part[c] = f0 * f0 + f1 * f1 + f2 * f2 + f3 * f3;
        }
#pragma unroll
        for (int c = 0; c < 4; c++) {
            float s = part[c];
            s += __shfl_xor_sync(0xFFFFFFFFu, s, 1);
            s += __shfl_xor_sync(0xFFFFFFFFu, s, 2);
            s += __shfl_xor_sync(0xFFFFFFFFu, s, 4);
            s += __shfl_xor_sync(0xFFFFFFFFu, s, 8);
            if ((tid & 15) == 0)
                g_cm_part[iblk][j0 + (tid >> 4) + 16 * c] = s;
        }
        __threadfence();
        __syncthreads();
        if (tid == 0) atomicAdd(&g_flag[iblk], 1);
        return;
    }

    // ================= GEMM CTA (8 warps, 64x32 warp tiles, 3-stage) =================
    int bn0 = (bid >> 2) * 128, bm0 = (bid & 3) * 128;

    uint32_t raw = s2u(smraw);
    uint32_t sb = (raw + 1023) & ~1023u;
    char* smp = smraw + (sb - raw);

    int lane = tid & 31, wid = tid >> 5;
    int wm = (wid >> 2) * 64;
    int wn = (wid & 3) * 32;

    int q = lane >> 3, rr = lane & 7;
    uint32_t qk = (uint32_t)(q >> 1) * 16;
    uint32_t xr = (uint32_t)(rr << 4);
    int aRowL = wm + (q & 1) * 8 + rr;
    int bRowL = wn + (q & 1) * 8 + rr;

    float acc[4][4][4];
#pragma unroll
    for (int mt = 0; mt < 4; mt++)
#pragma unroll
        for (int n8 = 0; n8 < 4; n8++)
#pragma unroll
            for (int c = 0; c < 4; c++) acc[mt][n8][c] = 0.f;

#define LOADSTAGE(st, t)                                                          \
    {                                                                             \
        uint32_t base = sb + (uint32_t)(st) * STAGE_B;                            \
        size_t k0 = (size_t)(t) * 64;                                             \
        _Pragma("unroll")                                                         \
        for (int i = 0; i < 4; i++) {                                             \
            int fid = tid + 256 * i;                                              \
            int r = fid >> 3, c = fid & 7;                                        \
            uint32_t so = SWZ((uint32_t)(r * 128 + c * 16));                      \
            cpasync16(base + so, &g_Ah[(size_t)(bm0 + r) * N4K + k0 + c * 8]);    \
            cpasync16(base + 16384u + so,                                         \
                      &g_Mth[(size_t)(bn0 + r) * N4K + k0 + c * 8]);              \
        }                                                                         \
    }
#define COMMIT() asm volatile("cp.async.commit_group;" ::: "memory")

    waitflag(0);
    LOADSTAGE(0, 0); COMMIT();
    waitflag(1);
    LOADSTAGE(1, 1); COMMIT();

    int cur = 0, nxt = 2;
    for (int t = 0; t < NKT; t++) {
        asm volatile("cp.async.wait_group 1;" ::: "memory");
        __syncthreads();
        if (t + 2 < NKT) { waitflag(t + 2); LOADSTAGE(nxt, t + 2); }
        COMMIT();

        uint32_t sa = sb + (uint32_t)cur * STAGE_B;
        uint32_t sB = sa + 16384u;
#pragma unroll
        for (int ks = 0; ks < 4; ks++) {
            uint32_t kb = ((uint32_t)(ks * 32) + qk) ^ xr;
            uint32_t a[4][4], b[2][4];
#pragma unroll
            for (int mt = 0; mt < 4; mt++)
                ldsm4(a[mt][0], a[mt][1], a[mt][2], a[mt][3],
                      sa + (uint32_t)(aRowL + mt * 16) * 128 + kb);
#pragma unroll
            for (int nt = 0; nt < 2; nt++)
                ldsm4(b[nt][0], b[nt][1], b[nt][2], b[nt][3],
                      sB + (uint32_t)(bRowL + nt * 16) * 128 + kb);
#pragma unroll
            for (int mt = 0; mt < 4; mt++)
#pragma unroll
                for (int n8 = 0; n8 < 4; n8++)
                    mma_f16(acc[mt][n8][0], acc[mt][n8][1], acc[mt][n8][2], acc[mt][n8][3],
                            a[mt][0], a[mt][1], a[mt][2], a[mt][3],
                            b[n8 >> 1][n8 & 1], b[n8 >> 1][(n8 & 1) + 2]);
        }
        cur = (cur == 2) ? 0 : cur + 1;
        nxt = (nxt == 2) ? 0 : nxt + 1;
    }

    // ---- invcmn finalize (all builds done: flag[63]==64 was consumed) ----
    asm volatile("cp.async.wait_group 0;" ::: "memory");
    __syncthreads();
    float* sic = (float*)smp;                  // reuse stage 0
    {
        int c = tid >> 1, ph = tid & 1;
        float s = 0.f;
#pragma unroll
        for (int p = 0; p < 32; p++) s += __ldcg(&g_cm_part[2 * p + ph][bn0 + c]);
        s += __shfl_xor_sync(0xFFFFFFFFu, s, 1);
        if (ph == 0) sic[c] = 1.0f / fmaxf(sqrtf(s), EPSV);
    }
    __syncthreads();

    // ---- epilogue: fold row + column norms, write fp32 ----
    int g4 = lane >> 2, t4 = lane & 3;
#pragma unroll
    for (int mt = 0; mt < 4; mt++) {
        int row0 = bm0 + wm + mt * 16 + g4;
        int row1 = row0 + 8;
        float ir0 = g_invrn[row0], ir1 = g_invrn[row1];
#pragma unroll
        for (int n8 = 0; n8 < 4; n8++) {
            int cl = wn + n8 * 8 + 2 * t4;
            int col = bn0 + cl;
            float c0 = sic[cl], c1 = sic[cl + 1];
            float2 v0 = make_float2(acc[mt][n8][0] * ir0 * c0, acc[mt][n8][1] * ir0 * c1);
            float2 v1 = make_float2(acc[mt][n8][2] * ir1 * c0, acc[mt][n8][3] * ir1 * c1);
            *(float2*)&out[(size_t)row0 * N4K + col] = v0;
            *(float2*)&out[(size_t)row1 * N4K + col] = v1;
        }
    }
}

// ---------------- launch ----------------
extern "C" void kernel_launch(void* const* d_in, const int* in_sizes, int n_in,
                              void* d_out, int out_size) {
    const float* x   = (const float*)d_in[0];   // (512, 4096)
    const float* w   = (const float*)d_in[1];   // (4096, 4096)
    const float* qf  = (const float*)d_in[2];   // (4096, 4096)
    const int*   qit = (const int*)d_in[3];     // (4096,)
    const int*   it  = (const int*)d_in[4];     // scalar
    float* out = (float*)d_out;                 // (512, 4096) fp32

    cudaFuncSetAttribute(k_main, cudaFuncAttributeMaxDynamicSharedMemorySize, SMEM_DYN);

    k_pre<<<320, 256>>>(x, w, qit, it);
    k_main<<<128 + 64 * 64, 256, SMEM_DYN>>>(w, qf, out);
}

// round 15
// speedup vs baseline: 1.5809x; 1.3376x over previous
#include <cuda_runtime.h>
#include <cuda_fp16.h>
#include <cstdint>

#define EPSV 1e-5f
#define N4K  4096
#define BROWS 512

// ---------------- scratch (static __device__: allocation-free) ----------------
__device__ __half g_Mth[(size_t)N4K * N4K];   // injected matrix, TRANSPOSED [j][i], fp16
__device__ __half g_Ah[(size_t)BROWS * N4K];  // x rounded to fp16
__device__ float g_cw_part[32][N4K];          // partial col sumsq of weight (32 splits)
__device__ float g_cm_part[64][N4K];          // partial col sumsq of Mth
__device__ float g_invrn[BROWS];
__device__ float g_ql[N4K];

// ---------------- helpers ----------------
__device__ __forceinline__ uint32_t s2u(const void* p) {
    uint32_t a;
    asm("{ .reg .u64 t; cvta.to.shared.u64 t, %1; cvt.u32.u64 %0, t; }" : "=r"(a) : "l"(p));
    return a;
}
__device__ __forceinline__ void ldsm4(uint32_t& r0, uint32_t& r1, uint32_t& r2,
                                      uint32_t& r3, uint32_t addr) {
    asm volatile("ldmatrix.sync.aligned.m8n8.x4.shared.b16 {%0,%1,%2,%3}, [%4];"
                 : "=r"(r0), "=r"(r1), "=r"(r2), "=r"(r3) : "r"(addr));
}
__device__ __forceinline__ void mma_f16(float& d0, float& d1, float& d2, float& d3,
                                        uint32_t a0, uint32_t a1, uint32_t a2, uint32_t a3,
                                        uint32_t b0, uint32_t b1) {
    asm volatile(
        "mma.sync.aligned.m16n8k16.row.col.f32.f16.f16.f32 "
        "{%0,%1,%2,%3}, {%4,%5,%6,%7}, {%8,%9}, {%0,%1,%2,%3};"
        : "+f"(d0), "+f"(d1), "+f"(d2), "+f"(d3)
        : "r"(a0), "r"(a1), "r"(a2), "r"(a3), "r"(b0), "r"(b1));
}
__device__ __forceinline__ void cpasync16(uint32_t dst, const void* src) {
    asm volatile("cp.async.cg.shared.global [%0], [%1], 16;" :: "r"(dst), "l"(src) : "memory");
}
#define SWZ(o) ((o) ^ (((o) >> 3) & 0x70))

// ---------------- K1: fused rownorm(x)+fp16  AND  colsq(w)+ql (32 splits) ----------------
__global__ void k_pre(const float* __restrict__ x, const float* __restrict__ w,
                      const int* __restrict__ qit, const int* __restrict__ iters) {
    int blk = blockIdx.x;
    if (blk < 64) {
        int wp = threadIdx.x >> 5, lid = threadIdx.x & 31;
        int b = blk * 8 + wp;
        const float4* p = (const float4*)(x + (size_t)b * N4K);
        __half* hrow = g_Ah + (size_t)b * N4K;
        float s = 0.f;
#pragma unroll
        for (int i = 0; i < 32; i++) {
            float4 v = p[lid + i * 32];
            s += v.x * v.x + v.y * v.y + v.z * v.z + v.w * v.w;
            __half2 h0 = __floats2half2_rn(v.x, v.y);
            __half2 h1 = __floats2half2_rn(v.z, v.w);
            uint2 u; u.x = *(uint32_t*)&h0; u.y = *(uint32_t*)&h1;
            *(uint2*)&hrow[(size_t)(lid + i * 32) * 4] = u;
        }
#pragma unroll
        for (int o = 16; o; o >>= 1) s += __shfl_xor_sync(0xFFFFFFFFu, s, o);
        if (lid == 0) g_invrn[b] = 1.0f / fmaxf(sqrtf(s), EPSV);
    } else {
        int jb = blk - 64;
        int j = (jb & 15) * 256 + threadIdx.x;
        int s = jb >> 4;                      // 32 splits of 128 rows
        if (s == 0) {
            int it = *iters + 1;
            bool active = (it - qit[j]) <= 200;
            g_ql[j] = ((it > 8000) && active) ? 0.15f : 0.0f;
        }
        const float* p = w + (size_t)(s * 128) * N4K + j;
        float acc = 0.f;
#pragma unroll 16
        for (int r = 0; r < 128; r++) { float v = p[(size_t)r * N4K]; acc += v * v; }
        g_cw_part[s][j] = acc;
    }
}

// ---------------- K2: build Mth[j][i] fp16 + column sumsq partials (vectorized) ----------------
__global__ __launch_bounds__(256) void k_build(const float* __restrict__ w,
                                               const float* __restrict__ qf) {
    __shared__ float swt[64][68];              // [j-local][i-local]
    __shared__ float sicw[64];
    int tid = threadIdx.x;
    int i0 = blockIdx.x * 64, j0 = blockIdx.y * 64;

    if (tid < 64) {
        float s = 0.f;
#pragma unroll
        for (int p = 0; p < 32; p++) s += g_cw_part[p][j0 + tid];
        sicw[tid] = 1.0f / fmaxf(sqrtf(s), EPSV);
    }
#pragma unroll
    for (int c = 0; c < 4; c++) {
        int chunk = tid + 256 * c;
        int il = chunk >> 4, jq = (chunk & 15) * 4;
        float4 v = *(const float4*)&w[(size_t)(i0 + il) * N4K + j0 + jq];
        swt[jq + 0][il] = v.x; swt[jq + 1][il] = v.y;
        swt[jq + 2][il] = v.z; swt[jq + 3][il] = v.w;
    }
    __syncthreads();

    int iq = (tid & 15) * 4;
    float4 q4 = *(const float4*)&g_ql[i0 + iq];
    float4 o4 = make_float4(1.f - q4.x, 1.f - q4.y, 1.f - q4.z, 1.f - q4.w);
    float part[4];
#pragma unroll
    for (int c = 0; c < 4; c++) {
        int jl = (tid >> 4) + 16 * c;
        int j = j0 + jl;
        float icw = sicw[jl];
        float4 wv = *(const float4*)&swt[jl][iq];
        float4 qv = *(const float4*)&qf[(size_t)j * N4K + i0 + iq];
        float m0 = wv.x * icw * o4.x + qv.x * q4.x;
        float m1 = wv.y * icw * o4.y + qv.y * q4.y;
        float m2 = wv.z * icw * o4.z + qv.z * q4.z;
        float m3 = wv.w * icw * o4.w + qv.w * q4.w;
        __half2 h0 = __floats2half2_rn(m0, m1);
        __half2 h1 = __floats2half2_rn(m2, m3);
        uint2 u; u.x = *(uint32_t*)&h0; u.y = *(uint32_t*)&h1;
        *(uint2*)&g_Mth[(size_t)j * N4K + i0 + iq] = u;
        float f0 = __low2float(h0), f1 = __high2float(h0);
        float f2 = __low2float(h1), f3 = __high2float(h1);
        part[c] = f0 * f0 + f1 * f1 + f2 * f2 + f3 * f3;
    }
#pragma unroll
    for (int c = 0; c < 4; c++) {
        float s = part[c];
        s += __shfl_xor_sync(0xFFFFFFFFu, s, 1);
        s += __shfl_xor_sync(0xFFFFFFFFu, s, 2);
        s += __shfl_xor_sync(0xFFFFFFFFu, s, 4);
        s += __shfl_xor_sync(0xFFFFFFFFu, s, 8);
        if ((tid & 15) == 0)
            g_cm_part[blockIdx.x][j0 + (tid >> 4) + 16 * c] = s;
    }
}

// ---------------- K3: fp16 mma.sync GEMM, 512 threads (+ inline invcmn) ----------------
// BM=128, BN=128, BK=64; 16 warps (4m x 4n), warp tile 32x32, m16n8k16.
// 4-stage cp.async pipeline, 32KB/stage. (R9 config: benched 59.9us)
static constexpr int SMEM_DYN = 1024 + 4 * 32768 + 512;
static constexpr int NKT = 64;                 // k-tiles of 64

__global__ __launch_bounds__(512, 1)
void k_gemm_mma(float* __restrict__ out) {
    extern __shared__ char smraw[];
    uint32_t raw = s2u(smraw);
    uint32_t sb = (raw + 1023) & ~1023u;       // 1024-aligned base
    char* smp = smraw + (sb - raw);
    float* sic = (float*)(smp + 4 * 32768);    // 128 floats: invcmn slice

    int tid = threadIdx.x;
    int lane = tid & 31, wid = tid >> 5;
    int wm = (wid >> 2) * 32;                  // warp m offset (0..96)
    int wn = (wid & 3) * 32;                   // warp n offset (0..96)
    int bn0 = blockIdx.x * 128, bm0 = blockIdx.y * 128;

    // ldmatrix per-lane addressing
    int q = lane >> 3, rr = lane & 7;
    uint32_t qk = (uint32_t)(q >> 1) * 16;     // +16B for high-k quads
    uint32_t xr = (uint32_t)(rr << 4);         // swizzle XOR
    int aRowL = wm + (q & 1) * 8 + rr;
    int bRowL = wn + (q & 1) * 8 + rr;

    float acc[2][4][4];
#pragma unroll
    for (int mt = 0; mt < 2; mt++)
#pragma unroll
        for (int n8 = 0; n8 < 4; n8++)
#pragma unroll
            for (int c = 0; c < 4; c++) acc[mt][n8][c] = 0.f;

#define LOADSTAGE(st, t)                                                          \
    {                                                                             \
        size_t k0 = (size_t)(t) * 64;                                             \
        uint32_t sa = sb + (uint32_t)(st) * 32768u;                               \
        _Pragma("unroll")                                                         \
        for (int i = 0; i < 2; i++) {                                             \
            int fid = tid + 512 * i;                                              \
            int r = fid >> 3, c = fid & 7;                                        \
            uint32_t so = SWZ((uint32_t)(r * 128 + c * 16));                      \
            cpasync16(sa + so, &g_Ah[(size_t)(bm0 + r) * N4K + k0 + c * 8]);      \
            cpasync16(sa + 16384u + so,                                           \
                      &g_Mth[(size_t)(bn0 + r) * N4K + k0 + c * 8]);              \
        }                                                                         \
    }
#define COMMIT() asm volatile("cp.async.commit_group;" ::: "memory")

    LOADSTAGE(0, 0); COMMIT();
    LOADSTAGE(1, 1); COMMIT();
    LOADSTAGE(2, 2); COMMIT();

    // ---- invcmn finalize for this CTA's 128 columns (overlaps with cp.async) ----
    {
        int c = tid >> 2, ph = tid & 3;
        float s = 0.f;
#pragma unroll
        for (int p = 0; p < 16; p++) s += g_cm_part[4 * p + ph][bn0 + c];
        s += __shfl_xor_sync(0xFFFFFFFFu, s, 1);
        s += __shfl_xor_sync(0xFFFFFFFFu, s, 2);
        if (ph == 0) sic[c] = 1.0f / fmaxf(sqrtf(s), EPSV);
    }

    for (int t = 0; t < NKT; t++) {
        asm volatile("cp.async.wait_group 2;" ::: "memory");
        __syncthreads();
        if (t + 3 < NKT) { LOADSTAGE((t + 3) & 3, t + 3); }
        COMMIT();

        uint32_t sa = sb + (uint32_t)(t & 3) * 32768u;
        uint32_t sB = sa + 16384u;
#pragma unroll
        for (int ks = 0; ks < 4; ks++) {
            uint32_t kb = ((uint32_t)(ks * 32) + qk) ^ xr;
            uint32_t a[2][4], b[2][4];
#pragma unroll
            for (int mt = 0; mt < 2; mt++)
                ldsm4(a[mt][0], a[mt][1], a[mt][2], a[mt][3],
                      sa + (uint32_t)(aRowL + mt * 16) * 128 + kb);
#pragma unroll
            for (int nt = 0; nt < 2; nt++)
                ldsm4(b[nt][0], b[nt][1], b[nt][2], b[nt][3],
                      sB + (uint32_t)(bRowL + nt * 16) * 128 + kb);
#pragma unroll
            for (int mt = 0; mt < 2; mt++)
#pragma unroll
                for (int n8 = 0; n8 < 4; n8++)
                    mma_f16(acc[mt][n8][0], acc[mt][n8][1], acc[mt][n8][2], acc[mt][n8][3],
                            a[mt][0], a[mt][1], a[mt][2], a[mt][3],
                            b[n8 >> 1][n8 & 1], b[n8 >> 1][(n8 & 1) + 2]);
        }
    }

    // ---- epilogue: fold row + column norms, write fp32 ----
    int g4 = lane >> 2, t4 = lane & 3;
#pragma unroll
    for (int mt = 0; mt < 2; mt++) {
        int row0 = bm0 + wm + mt * 16 + g4;
        int row1 = row0 + 8;
        float ir0 = g_invrn[row0], ir1 = g_invrn[row1];
#pragma unroll
        for (int n8 = 0; n8 < 4; n8++) {
            int cl = wn + n8 * 8 + 2 * t4;
            int col = bn0 + cl;
            float c0 = sic[cl], c1 = sic[cl + 1];
            float2 v0 = make_float2(acc[mt][n8][0] * ir0 * c0, acc[mt][n8][1] * ir0 * c1);
            float2 v1 = make_float2(acc[mt][n8][2] * ir1 * c0, acc[mt][n8][3] * ir1 * c1);
            *(float2*)&out[(size_t)row0 * N4K + col] = v0;
            *(float2*)&out[(size_t)row1 * N4K + col] = v1;
        }
    }
}

// ---------------- launch ----------------
extern "C" void kernel_launch(void* const* d_in, const int* in_sizes, int n_in,
                              void* d_out, int out_size) {
    const float* x   = (const float*)d_in[0];   // (512, 4096)
    const float* w   = (const float*)d_in[1];   // (4096, 4096)
    const float* qf  = (const float*)d_in[2];   // (4096, 4096)
    const int*   qit = (const int*)d_in[3];     // (4096,)
    const int*   it  = (const int*)d_in[4];     // scalar
    float* out = (float*)d_out;                 // (512, 4096) fp32

    cudaFuncSetAttribute(k_gemm_mma, cudaFuncAttributeMaxDynamicSharedMemorySize, SMEM_DYN);

    k_pre<<<576, 256>>>(x, w, qit, it);
    k_build<<<dim3(64, 64), 256>>>(w, qf);
    k_gemm_mma<<<dim3(32, 4), 512, SMEM_DYN>>>(out);
}